// round 2
// baseline (speedup 1.0000x reference)
#include <cuda_runtime.h>

// Problem constants (shapes fixed by the reference: N=20000, E=100000)
#define NMAX 20000
#define EMAX 100000
constexpr int IN_DIM = 128;
constexpr int HID    = 64;
constexpr int LAT    = 32;
constexpr int EDIM   = 16;

// ---------------- scratch (device globals; no cudaMalloc allowed) -----------
__device__ float g_h[NMAX * HID];      // relu(x @ lin_in_w + b)
__device__ float g_num[NMAX * HID];    // scatter-sum of messages
__device__ float g_cnt[NMAX];          // in-degree per dst
__device__ int   g_src[EMAX];
__device__ int   g_dst[EMAX];
__device__ int   g_is64;

// ---------------- packed f32x2 helpers (sm_100+) ----------------------------
typedef unsigned long long u64;

__device__ __forceinline__ u64 pk2(float x, float y) {
    u64 r; asm("mov.b64 %0,{%1,%2};" : "=l"(r) : "f"(x), "f"(y)); return r;
}
__device__ __forceinline__ void upk2(u64 v, float& x, float& y) {
    asm("mov.b64 {%0,%1},%2;" : "=f"(x), "=f"(y) : "l"(v));
}
__device__ __forceinline__ u64 ffma2(u64 a, u64 b, u64 c) {
    u64 d; asm("fma.rn.f32x2 %0,%1,%2,%3;" : "=l"(d) : "l"(a), "l"(b), "l"(c)); return d;
}
__device__ __forceinline__ u64 fadd2(u64 a, u64 b) {
    u64 d; asm("add.rn.f32x2 %0,%1,%2;" : "=l"(d) : "l"(a), "l"(b)); return d;
}
// 128-bit shared load (two packed f32x2) — broadcast across the warp
__device__ __forceinline__ void lds128(unsigned addr, u64& a, u64& b) {
    asm volatile("ld.shared.v2.b64 {%0,%1},[%2];" : "=l"(a), "=l"(b) : "r"(addr));
}

// ---------------- dtype detect: edge_index int64 vs int32 -------------------
// Values are in [0, N) >= 0, so an int64 (LE) buffer has every odd int32 word
// == 0. For real int32 data those words are uniform node ids in [0, 20000):
// P(32 consecutive samples all zero) ~ (1/20000)^32 ~ 0.
__global__ void detect_kernel(const int* __restrict__ ei) {
    int is64 = 1;
#pragma unroll
    for (int k = 0; k < 32; k++)
        if (ei[2 * k + 1] != 0) is64 = 0;
    g_is64 = is64;
}

__global__ void zero_kernel(int N) {
    int tot = N * HID;
    for (int i = blockIdx.x * blockDim.x + threadIdx.x; i < tot; i += gridDim.x * blockDim.x)
        g_num[i] = 0.f;
    for (int j = blockIdx.x * blockDim.x + threadIdx.x; j < N; j += gridDim.x * blockDim.x)
        g_cnt[j] = 0.f;
}

__global__ void convert_kernel(const void* __restrict__ ei, int E) {
    int e = blockIdx.x * blockDim.x + threadIdx.x;
    if (e >= E) return;
    int s, d;
    if (g_is64) {
        const long long* p = (const long long*)ei;
        s = (int)p[e]; d = (int)p[E + e];
    } else {
        const int* p = (const int*)ei;
        s = p[e]; d = p[E + e];
    }
    g_src[e] = s; g_dst[e] = d;
    atomicAdd(&g_cnt[d], 1.f);
}

// ---------------- h = relu(x @ lin_in_w + lin_in_b) -------------------------
// 256 threads / block, 16 nodes / block. Weights + x rows staged in smem.
__global__ void __launch_bounds__(256) hin_kernel(
    const float* __restrict__ x, const float* __restrict__ w,
    const float* __restrict__ b, int N) {
    __shared__ float ws[IN_DIM][HID];   // 32 KB, row-major like w
    __shared__ float xs[16][IN_DIM];    // 8 KB
    int tid = threadIdx.x;
    for (int idx = tid; idx < IN_DIM * HID / 4; idx += 256)
        ((float4*)ws)[idx] = ((const float4*)w)[idx];
    int base = blockIdx.x * 16;
    for (int idx = tid; idx < 16 * IN_DIM / 4; idx += 256) {
        int nl = idx >> 5, j = idx & 31;
        int n = base + nl;
        if (n < N) ((float4*)xs[nl])[j] = ((const float4*)(x + (size_t)n * IN_DIM))[j];
    }
    __syncthreads();
    int o = tid & 63;
    float bo = b[o];
    for (int nl = tid >> 6; nl < 16; nl += 4) {
        int n = base + nl;
        if (n >= N) continue;
        float acc = bo;
#pragma unroll
        for (int d = 0; d < IN_DIM; d++) acc += xs[nl][d] * ws[d][o];
        g_h[(size_t)n * HID + o] = fmaxf(acc, 0.f);
    }
}

// ---------------- fused edge kernel -----------------------------------------
// One thread per edge; 128 edges per block. ker_w staged in smem in chunks of
// 4 h-columns (16KB). Inner math in packed fma.rn.f32x2 (2 fp32 FMA / issue).
// msg[e,o] = sum_h h_src[h] * relu( sum_d a[d]*K[d, h*64+o] + b[h*64+o] )
__global__ void __launch_bounds__(128) edge_kernel(
    const float* __restrict__ edge_attr, const float* __restrict__ ker_w,
    const float* __restrict__ ker_b, int E) {
    __shared__ __align__(16) float ks[EDIM][256];  // [d][4h * 64o] chunk, 16 KB
    __shared__ __align__(16) float kb[256];        // bias chunk
    unsigned ksb = (unsigned)__cvta_generic_to_shared(&ks[0][0]);
    unsigned kbb = (unsigned)__cvta_generic_to_shared(&kb[0]);

    int e = blockIdx.x * 128 + threadIdx.x;
    bool act = e < E;

    u64 a2[EDIM];   // (a[d], a[d]) packed
    int src = 0, dst = 0;
    if (act) {
        const float4* ea = (const float4*)(edge_attr + (size_t)e * EDIM);
#pragma unroll
        for (int i = 0; i < 4; i++) {
            float4 q = ea[i];
            a2[4 * i + 0] = pk2(q.x, q.x);
            a2[4 * i + 1] = pk2(q.y, q.y);
            a2[4 * i + 2] = pk2(q.z, q.z);
            a2[4 * i + 3] = pk2(q.w, q.w);
        }
        src = g_src[e];
        dst = g_dst[e];
    }

    u64 msg2[32];
#pragma unroll
    for (int i = 0; i < 32; i++) msg2[i] = 0ULL;   // bits of (0.f, 0.f)

    const float* hb = g_h + (size_t)src * HID;

    for (int hc = 0; hc < HID; hc += 4) {
        __syncthreads();
        // stage ker_w[:, hc*64 .. hc*64+255] and bias
        for (int idx = threadIdx.x; idx < EDIM * 64; idx += 128) {
            int d = idx >> 6, j = idx & 63;
            ((float4*)ks[d])[j] =
                ((const float4*)(ker_w + (size_t)d * (HID * HID) + hc * HID))[j];
        }
        if (threadIdx.x < 64)
            ((float4*)kb)[threadIdx.x] = ((const float4*)(ker_b + hc * HID))[threadIdx.x];
        __syncthreads();
        if (!act) continue;  // rejoins at next iteration's barrier

        float4 hs4 = *(const float4*)(hb + hc);   // gathered h_src[hc..hc+3]
        float hv[4] = {hs4.x, hs4.y, hs4.z, hs4.w};
#pragma unroll
        for (int h = 0; h < 4; h++) {
            u64 h2 = pk2(hv[h], hv[h]);
            unsigned kso = ksb + (unsigned)(h * 64 * 4);
            unsigned kbo = kbb + (unsigned)(h * 64 * 4);
#pragma unroll
            for (int oq = 0; oq < 16; oq++) {       // 4 outputs per oq
                u64 acc0, acc1;
                lds128(kbo + oq * 16, acc0, acc1);  // bias pair-of-pairs
                u64 b0 = 0ULL, b1 = 0ULL;
#pragma unroll
                for (int d = 0; d < EDIM; d += 2) {
                    u64 p0, p1, p2, p3;
                    lds128(kso + d * 1024 + oq * 16, p0, p1);
                    lds128(kso + (d + 1) * 1024 + oq * 16, p2, p3);
                    acc0 = ffma2(a2[d], p0, acc0);
                    acc1 = ffma2(a2[d], p1, acc1);
                    b0   = ffma2(a2[d + 1], p2, b0);
                    b1   = ffma2(a2[d + 1], p3, b1);
                }
                u64 w0 = fadd2(acc0, b0);
                u64 w1 = fadd2(acc1, b1);
                float x0, x1, x2, x3;
                upk2(w0, x0, x1); upk2(w1, x2, x3);
                w0 = pk2(fmaxf(x0, 0.f), fmaxf(x1, 0.f));
                w1 = pk2(fmaxf(x2, 0.f), fmaxf(x3, 0.f));
                msg2[2 * oq]     = ffma2(h2, w0, msg2[2 * oq]);
                msg2[2 * oq + 1] = ffma2(h2, w1, msg2[2 * oq + 1]);
            }
        }
    }

    if (act) {
        float* db = g_num + (size_t)dst * HID;
#pragma unroll
        for (int i = 0; i < 32; i++) {
            float v0, v1;
            upk2(msg2[i], v0, v1);
            atomicAdd(db + 2 * i, v0);
            atomicAdd(db + 2 * i + 1, v1);
        }
    }
}

// ---------------- final: relu(h@root_w + num/cnt + conv_b) -> mu/logvar -----
// 256 threads = 4 groups of 64; each group handles one node at a time via a
// named barrier; weights staged once per block (16 nodes / block).
__global__ void __launch_bounds__(256) final_kernel(
    const float* __restrict__ root_w, const float* __restrict__ conv_b,
    const float* __restrict__ mu_w, const float* __restrict__ mu_b,
    const float* __restrict__ lv_w, const float* __restrict__ lv_b,
    float* __restrict__ out, int N) {
    __shared__ float rw[HID][HID];   // 16 KB
    __shared__ float mw[HID][LAT];   // 8 KB
    __shared__ float lw[HID][LAT];   // 8 KB
    __shared__ float hv[4][HID];
    __shared__ float tv[4][HID];
    int tid = threadIdx.x;
    for (int idx = tid; idx < HID * HID / 4; idx += 256)
        ((float4*)rw)[idx] = ((const float4*)root_w)[idx];
    for (int idx = tid; idx < HID * LAT / 4; idx += 256)
        ((float4*)mw)[idx] = ((const float4*)mu_w)[idx];
    for (int idx = tid; idx < HID * LAT / 4; idx += 256)
        ((float4*)lw)[idx] = ((const float4*)lv_w)[idx];
    __syncthreads();

    int g = tid >> 6;
    int o = tid & 63;
    float cb = conv_b[o];
    float hb = (o < LAT) ? mu_b[o] : lv_b[o - LAT];

    for (int nl = g; nl < 16; nl += 4) {
        int n = blockIdx.x * 16 + nl;
        bool valid = n < N;
        if (valid) hv[g][o] = g_h[(size_t)n * HID + o];
        asm volatile("bar.sync %0, 64;" :: "r"(g + 1) : "memory");
        if (valid) {
            float inv = 1.f / fmaxf(g_cnt[n], 1.f);
            float acc = cb + g_num[(size_t)n * HID + o] * inv;
#pragma unroll
            for (int h = 0; h < HID; h++) acc += hv[g][h] * rw[h][o];
            tv[g][o] = fmaxf(acc, 0.f);
        }
        asm volatile("bar.sync %0, 64;" :: "r"(g + 1) : "memory");
        if (valid) {
            if (o < LAT) {
                float m = hb;
#pragma unroll
                for (int k = 0; k < HID; k++) m += tv[g][k] * mw[k][o];
                out[(size_t)n * LAT + o] = m;
            } else {
                int l = o - LAT;
                float m = hb;
#pragma unroll
                for (int k = 0; k < HID; k++) m += tv[g][k] * lw[k][l];
                out[(size_t)N * LAT + (size_t)n * LAT + l] = m;
            }
        }
        asm volatile("bar.sync %0, 64;" :: "r"(g + 1) : "memory");
    }
}

// ---------------- launcher ---------------------------------------------------
extern "C" void kernel_launch(void* const* d_in, const int* in_sizes, int n_in,
                              void* d_out, int out_size) {
    const float* x      = (const float*)d_in[0];
    const void*  ei     = d_in[1];
    const float* ea     = (const float*)d_in[2];
    const float* lin_w  = (const float*)d_in[3];
    const float* lin_b  = (const float*)d_in[4];
    const float* ker_w  = (const float*)d_in[5];
    const float* ker_b  = (const float*)d_in[6];
    const float* root_w = (const float*)d_in[7];
    const float* conv_b = (const float*)d_in[8];
    const float* mu_w   = (const float*)d_in[9];
    const float* mu_b   = (const float*)d_in[10];
    const float* lv_w   = (const float*)d_in[11];
    const float* lv_b   = (const float*)d_in[12];

    int N = in_sizes[0] / IN_DIM;
    int E = in_sizes[1] / 2;   // element count is 2E for either int dtype
    if (N > NMAX) N = NMAX;    // scratch capacity guard (shapes are fixed,
    if (E > EMAX) E = EMAX;    // but bounded-wrong beats OOB for debugging)

    detect_kernel<<<1, 1>>>((const int*)ei);
    zero_kernel<<<256, 256>>>(N);
    convert_kernel<<<(E + 255) / 256, 256>>>(ei, E);
    hin_kernel<<<(N + 15) / 16, 256>>>(x, lin_w, lin_b, N);
    edge_kernel<<<(E + 127) / 128, 128>>>(ea, ker_w, ker_b, E);
    final_kernel<<<(N + 15) / 16, 256>>>(root_w, conv_b, mu_w, mu_b, lv_w, lv_b,
                                         (float*)d_out, N);
}

// round 4
// speedup vs baseline: 2.0831x; 2.0831x over previous
#include <cuda_runtime.h>
#include <cuda_bf16.h>
#include <cstdint>

// Problem constants (shapes fixed by the reference: N=20000, E=100000)
#define NMAX 20000
#define EMAX 100000
constexpr int IN_DIM = 128;
constexpr int HID    = 64;
constexpr int LAT    = 32;
constexpr int EDIM   = 16;

// ---------------- edge kernel geometry --------------------------------------
// 256 threads = 8 warps; 128 edges per CTA (warp w owns edges 16w..16w+15).
// N dimension = 4096 outputs = 512 n-steps of 8 cols; 16 chunks of 256 cols.
// B (ker_w hi/lo bf16) prepped in global with 48B row stride (24 bf16, 16 used)
// -> conflict-free ldmatrix, flat 16B-copyable chunks.
constexpr int B_CHUNK_BYTES = 256 * 48;          // per term: 12288
constexpr int B_SLOT_BYTES  = 2 * B_CHUNK_BYTES; // hi + lo:  24576
constexpr int NCHUNK        = 16;

// dynamic smem layout (16B aligned blocks)
constexpr int SMB_BIAS = 0;                       // 4096 f32 = 16384
constexpr int SMB_H    = 16384;                   // 128 rows * 272B = 34816
constexpr int SMB_A    = SMB_H + 34816;           // 2 terms * 128*48 = 12288
constexpr int SMB_B    = SMB_A + 12288;           // 2 slots * 24576 = 49152
constexpr int SMEM_EDGE = SMB_B + 2 * B_SLOT_BYTES;   // 112640

// ---------------- scratch (device globals; no cudaMalloc allowed) -----------
__device__ float g_h[NMAX * HID];
__device__ float g_num[NMAX * HID];
__device__ float g_cnt[NMAX];
__device__ int   g_src[EMAX];
__device__ int   g_dst[EMAX];
__device__ int   g_is64;
__device__ __align__(16) unsigned char g_Bp[NCHUNK * B_SLOT_BYTES]; // 384KB

// ---------------- helpers ----------------------------------------------------
typedef unsigned long long u64;

__device__ __forceinline__ u64 pk2(float x, float y) {
    u64 r; asm("mov.b64 %0,{%1,%2};" : "=l"(r) : "f"(x), "f"(y)); return r;
}
__device__ __forceinline__ void upk2(u64 v, float& x, float& y) {
    asm("mov.b64 {%0,%1},%2;" : "=f"(x), "=f"(y) : "l"(v));
}
__device__ __forceinline__ u64 ffma2(u64 a, u64 b, u64 c) {
    u64 d; asm("fma.rn.f32x2 %0,%1,%2,%3;" : "=l"(d) : "l"(a), "l"(b), "l"(c)); return d;
}
__device__ __forceinline__ unsigned smem_u32(const void* p) {
    return (unsigned)__cvta_generic_to_shared(p);
}
__device__ __forceinline__ void cpasync16(unsigned dst, const void* src) {
    asm volatile("cp.async.ca.shared.global [%0], [%1], 16;" :: "r"(dst), "l"(src));
}
#define CP_COMMIT() asm volatile("cp.async.commit_group;" ::: "memory")
#define CP_WAIT0()  asm volatile("cp.async.wait_group 0;" ::: "memory")

#define LDMX2(r0, r1, addr) \
    asm volatile("ldmatrix.sync.aligned.m8n8.x2.shared.b16 {%0,%1},[%2];" \
                 : "=r"(r0), "=r"(r1) : "r"(addr))
#define LDMX4(r, addr) \
    asm volatile("ldmatrix.sync.aligned.m8n8.x4.shared.b16 {%0,%1,%2,%3},[%4];" \
                 : "=r"((r)[0]), "=r"((r)[1]), "=r"((r)[2]), "=r"((r)[3]) : "r"(addr))

#define MMA_BF16(c0, c1, c2, c3, a, b0, b1) \
    asm volatile("mma.sync.aligned.m16n8k16.row.col.f32.bf16.bf16.f32 " \
                 "{%0,%1,%2,%3},{%4,%5,%6,%7},{%8,%9},{%0,%1,%2,%3};" \
                 : "+f"(c0), "+f"(c1), "+f"(c2), "+f"(c3) \
                 : "r"((a)[0]), "r"((a)[1]), "r"((a)[2]), "r"((a)[3]), \
                   "r"(b0), "r"(b1))

// ---------------- setup kernels ----------------------------------------------
__global__ void detect_kernel(const int* __restrict__ ei) {
    int is64 = 1;
#pragma unroll
    for (int k = 0; k < 32; k++)
        if (ei[2 * k + 1] != 0) is64 = 0;
    g_is64 = is64;
}

__global__ void zero_kernel(int N) {
    int tot = N * HID;
    for (int i = blockIdx.x * blockDim.x + threadIdx.x; i < tot; i += gridDim.x * blockDim.x)
        g_num[i] = 0.f;
    for (int j = blockIdx.x * blockDim.x + threadIdx.x; j < N; j += gridDim.x * blockDim.x)
        g_cnt[j] = 0.f;
}

__global__ void convert_kernel(const void* __restrict__ ei, int E) {
    int e = blockIdx.x * blockDim.x + threadIdx.x;
    if (e >= E) return;
    int s, d;
    if (g_is64) {
        const long long* p = (const long long*)ei;
        s = (int)p[e]; d = (int)p[E + e];
    } else {
        const int* p = (const int*)ei;
        s = p[e]; d = p[E + e];
    }
    g_src[e] = s; g_dst[e] = d;
    atomicAdd(&g_cnt[d], 1.f);
}

// Build hi/lo bf16 B images: for chunk c, term t, row n(0..255), k(0..15):
// bf16 at g_Bp[(c*2+t)*12288 + n*48 + k*2]. Pad bytes (k16-23) stay zero
// (__device__ globals are zero-initialized).
__global__ void prep_kernel(const float* __restrict__ kw) {
    int idx = blockIdx.x * 256 + threadIdx.x;     // n*16 + k, 65536 total
    if (idx >= 4096 * 16) return;
    int n = idx >> 4, k = idx & 15;
    float v = kw[(size_t)k * 4096 + n];
    __nv_bfloat16 hi = __float2bfloat16_rn(v);
    __nv_bfloat16 lo = __float2bfloat16_rn(v - __bfloat162float(hi));
    int c = n >> 8, nl = n & 255;
    size_t base = (size_t)c * B_SLOT_BYTES + (size_t)nl * 48 + (size_t)k * 2;
    *(__nv_bfloat16*)(g_Bp + base)                 = hi;
    *(__nv_bfloat16*)(g_Bp + base + B_CHUNK_BYTES) = lo;
}

// ---------------- h = relu(x @ lin_in_w + lin_in_b) -------------------------
// 128 threads, 16 nodes/block; thread = (pair p, group g), 4 nodes per thread.
__global__ void __launch_bounds__(128) hin_kernel(
    const float* __restrict__ x, const float* __restrict__ w,
    const float* __restrict__ b, int N) {
    __shared__ u64   ws2[IN_DIM][32];   // (w[d][2p], w[d][2p+1])
    __shared__ float xs[16][IN_DIM];
    int tid = threadIdx.x;
    for (int i = tid; i < IN_DIM * 32; i += 128)
        ((u64*)ws2)[i] = ((const u64*)w)[i];
    int base = blockIdx.x * 16;
    for (int i = tid; i < 16 * 32; i += 128) {
        int nl = i >> 5, j = i & 31;
        int n = base + nl;
        if (n < N) ((float4*)xs[nl])[j] = ((const float4*)(x + (size_t)n * IN_DIM))[j];
    }
    __syncthreads();
    int p = tid & 31, g = tid >> 5;
    float2 b2 = ((const float2*)b)[p];
    u64 bias2 = pk2(b2.x, b2.y);
    u64 acc0 = bias2, acc1 = bias2, acc2 = bias2, acc3 = bias2;
#pragma unroll 8
    for (int d = 0; d < IN_DIM; d++) {
        u64 w2 = ws2[d][p];
        acc0 = ffma2(pk2(xs[g][d],      xs[g][d]),      w2, acc0);
        acc1 = ffma2(pk2(xs[g + 4][d],  xs[g + 4][d]),  w2, acc1);
        acc2 = ffma2(pk2(xs[g + 8][d],  xs[g + 8][d]),  w2, acc2);
        acc3 = ffma2(pk2(xs[g + 12][d], xs[g + 12][d]), w2, acc3);
    }
    u64 accs[4] = {acc0, acc1, acc2, acc3};
#pragma unroll
    for (int q = 0; q < 4; q++) {
        int n = base + g + 4 * q;
        if (n < N) {
            float v0, v1; upk2(accs[q], v0, v1);
            float2 r; r.x = fmaxf(v0, 0.f); r.y = fmaxf(v1, 0.f);
            *(float2*)(g_h + (size_t)n * HID + 2 * p) = r;
        }
    }
}

// ---------------- fused edge kernel (mma.sync bf16 3-term) -------------------
// msg[e,o] = sum_h h_src[e,h] * relu( (EA[e,:]@K)[h*64+o] + kb[h*64+o] )
__global__ void __launch_bounds__(256, 1) edge_kernel(
    const float* __restrict__ edge_attr, const float* __restrict__ ker_b, int E) {
    extern __shared__ __align__(16) unsigned char sm[];
    unsigned sb = smem_u32(sm);
    int tid = threadIdx.x, lane = tid & 31, w = tid >> 5;
    int blk = blockIdx.x;

    // stage bias (4096 f32)
    for (int i = tid; i < 1024; i += 256)
        ((float4*)(sm + SMB_BIAS))[i] = ((const float4*)ker_b)[i];

    // stage h rows (gather; row stride 272B = 68 floats -> conflict-free)
    for (int i = tid; i < 128 * 16; i += 256) {
        int r = i >> 4, q4 = i & 15;
        int e = blk * 128 + r;
        int s = (e < E) ? g_src[e] : 0;
        *(float4*)(sm + SMB_H + r * 272 + q4 * 16) =
            ((const float4*)(g_h + (size_t)s * HID))[q4];
    }

    // stage A rows (hi/lo bf16, 48B stride); zero rows for edges >= E
    if (tid < 128) {
        int e = blk * 128 + tid;
        float va[16];
        if (e < E) {
            const float4* p = (const float4*)(edge_attr + (size_t)e * EDIM);
#pragma unroll
            for (int i = 0; i < 4; i++) {
                float4 q4 = p[i];
                va[4*i] = q4.x; va[4*i+1] = q4.y; va[4*i+2] = q4.z; va[4*i+3] = q4.w;
            }
        } else {
#pragma unroll
            for (int i = 0; i < 16; i++) va[i] = 0.f;
        }
#pragma unroll
        for (int k = 0; k < 8; k++) {
            float v0 = va[2*k], v1 = va[2*k+1];
            __nv_bfloat16 h0 = __float2bfloat16_rn(v0);
            __nv_bfloat16 h1 = __float2bfloat16_rn(v1);
            __nv_bfloat162 hp; hp.x = h0; hp.y = h1;
            __nv_bfloat162 lp;
            lp.x = __float2bfloat16_rn(v0 - __bfloat162float(h0));
            lp.y = __float2bfloat16_rn(v1 - __bfloat162float(h1));
            *(__nv_bfloat162*)(sm + SMB_A + tid * 48 + k * 4)        = hp;
            *(__nv_bfloat162*)(sm + SMB_A + 6144 + tid * 48 + k * 4) = lp;
        }
    }

    // stage B chunk 0
    for (int i = tid; i < B_SLOT_BYTES / 16; i += 256)
        cpasync16(sb + SMB_B + i * 16, g_Bp + i * 16);
    CP_COMMIT();
    CP_WAIT0();
    __syncthreads();

    // A fragments (register resident for the whole kernel)
    unsigned a_hi[4], a_lo[4];
    {
        int rowA = (lane & 7) + ((lane >> 3) & 1) * 8;
        int koff = (lane >> 4) * 8;
        unsigned aaddr = sb + SMB_A + (unsigned)((w * 16 + rowA) * 48 + koff * 2);
        LDMX4(a_hi, aaddr);
        LDMX4(a_lo, aaddr + 6144);
    }

    int q = lane & 3;
    int row0 = lane >> 2;                       // warp-tile local row (0..7)
    unsigned hrow0 = sb + SMB_H + (unsigned)((w * 16 + row0) * 272);
    unsigned hrow1 = hrow0 + 8 * 272;
    unsigned boff  = (unsigned)((lane & 7) * 48 + ((lane & 8) ? 16 : 0));
    unsigned biasb = sb + SMB_BIAS + (unsigned)(q * 8);

    float msgA[16], msgB[16];
#pragma unroll
    for (int i = 0; i < 16; i++) { msgA[i] = 0.f; msgB[i] = 0.f; }

    for (int c = 0; c < NCHUNK; c++) {
        int slot = c & 1;
        if (c < NCHUNK - 1) {                   // prefetch next chunk
            const unsigned char* src = g_Bp + (size_t)(c + 1) * B_SLOT_BYTES;
            unsigned dstb = sb + SMB_B + (unsigned)(((c + 1) & 1) * B_SLOT_BYTES);
            for (int i = tid; i < B_SLOT_BYTES / 16; i += 256)
                cpasync16(dstb + i * 16, src + i * 16);
            CP_COMMIT();
        }
        unsigned bbase = sb + SMB_B + (unsigned)(slot * B_SLOT_BYTES) + boff;
#pragma unroll
        for (int hb = 0; hb < 4; hb++) {
            int h = c * 4 + hb;
            float hv0, hv1;
            asm("ld.shared.f32 %0,[%1];" : "=f"(hv0) : "r"(hrow0 + (unsigned)(h * 4)));
            asm("ld.shared.f32 %0,[%1];" : "=f"(hv1) : "r"(hrow1 + (unsigned)(h * 4)));
#pragma unroll
            for (int t = 0; t < 8; t++) {
                int jj = hb * 8 + t;            // n-step within chunk
                unsigned ba = bbase + (unsigned)(jj * 384);
                unsigned bh0, bh1, bl0, bl1;
                LDMX2(bh0, bh1, ba);
                LDMX2(bl0, bl1, ba + B_CHUNK_BYTES);
                float c0 = 0.f, c1 = 0.f, c2 = 0.f, c3 = 0.f;
                MMA_BF16(c0, c1, c2, c3, a_hi, bh0, bh1);
                MMA_BF16(c0, c1, c2, c3, a_lo, bh0, bh1);
                MMA_BF16(c0, c1, c2, c3, a_hi, bl0, bl1);
                float2 bb;
                asm("ld.shared.v2.f32 {%0,%1},[%2];"
                    : "=f"(bb.x), "=f"(bb.y)
                    : "r"(biasb + (unsigned)((c * 32 + jj) * 32)));
                float w0 = fmaxf(c0 + bb.x, 0.f);
                float w1 = fmaxf(c1 + bb.y, 0.f);
                float w2 = fmaxf(c2 + bb.x, 0.f);
                float w3 = fmaxf(c3 + bb.y, 0.f);
                msgA[t*2]     = fmaf(hv0, w0, msgA[t*2]);
                msgA[t*2 + 1] = fmaf(hv0, w1, msgA[t*2 + 1]);
                msgB[t*2]     = fmaf(hv1, w2, msgB[t*2]);
                msgB[t*2 + 1] = fmaf(hv1, w3, msgB[t*2 + 1]);
            }
        }
        if (c < NCHUNK - 1) CP_WAIT0();
        __syncthreads();
    }

    // scatter: each (edge, o) has a unique owner thread
    int e0 = blk * 128 + w * 16 + row0;
    if (e0 < E) {
        float* d = g_num + (size_t)g_dst[e0] * HID + 2 * q;
#pragma unroll
        for (int t = 0; t < 8; t++) {
            atomicAdd(d + 8 * t,     msgA[2 * t]);
            atomicAdd(d + 8 * t + 1, msgA[2 * t + 1]);
        }
    }
    int e1 = e0 + 8;
    if (e1 < E) {
        float* d = g_num + (size_t)g_dst[e1] * HID + 2 * q;
#pragma unroll
        for (int t = 0; t < 8; t++) {
            atomicAdd(d + 8 * t,     msgB[2 * t]);
            atomicAdd(d + 8 * t + 1, msgB[2 * t + 1]);
        }
    }
}

// ---------------- final: relu(h@root_w + num/cnt + conv_b) -> mu/logvar -----
__global__ void __launch_bounds__(256) final_kernel(
    const float* __restrict__ root_w, const float* __restrict__ conv_b,
    const float* __restrict__ mu_w, const float* __restrict__ mu_b,
    const float* __restrict__ lv_w, const float* __restrict__ lv_b,
    float* __restrict__ out, int N) {
    __shared__ float rw[HID][HID];
    __shared__ float mw[HID][LAT];
    __shared__ float lw[HID][LAT];
    __shared__ float hv[4][HID];
    __shared__ float tv[4][HID];
    int tid = threadIdx.x;
    for (int idx = tid; idx < HID * HID / 4; idx += 256)
        ((float4*)rw)[idx] = ((const float4*)root_w)[idx];
    for (int idx = tid; idx < HID * LAT / 4; idx += 256)
        ((float4*)mw)[idx] = ((const float4*)mu_w)[idx];
    for (int idx = tid; idx < HID * LAT / 4; idx += 256)
        ((float4*)lw)[idx] = ((const float4*)lv_w)[idx];
    __syncthreads();

    int g = tid >> 6;
    int o = tid & 63;
    float cb = conv_b[o];
    float hb = (o < LAT) ? mu_b[o] : lv_b[o - LAT];

    for (int nl = g; nl < 16; nl += 4) {
        int n = blockIdx.x * 16 + nl;
        bool valid = n < N;
        if (valid) hv[g][o] = g_h[(size_t)n * HID + o];
        asm volatile("bar.sync %0, 64;" :: "r"(g + 1) : "memory");
        if (valid) {
            float inv = 1.f / fmaxf(g_cnt[n], 1.f);
            float acc = cb + g_num[(size_t)n * HID + o] * inv;
#pragma unroll
            for (int h = 0; h < HID; h++) acc += hv[g][h] * rw[h][o];
            tv[g][o] = fmaxf(acc, 0.f);
        }
        asm volatile("bar.sync %0, 64;" :: "r"(g + 1) : "memory");
        if (valid) {
            if (o < LAT) {
                float m = hb;
#pragma unroll
                for (int k = 0; k < HID; k++) m += tv[g][k] * mw[k][o];
                out[(size_t)n * LAT + o] = m;
            } else {
                int l = o - LAT;
                float m = hb;
#pragma unroll
                for (int k = 0; k < HID; k++) m += tv[g][k] * lw[k][l];
                out[(size_t)N * LAT + (size_t)n * LAT + l] = m;
            }
        }
        asm volatile("bar.sync %0, 64;" :: "r"(g + 1) : "memory");
    }
}

// ---------------- launcher ---------------------------------------------------
extern "C" void kernel_launch(void* const* d_in, const int* in_sizes, int n_in,
                              void* d_out, int out_size) {
    const float* x      = (const float*)d_in[0];
    const void*  ei     = d_in[1];
    const float* ea     = (const float*)d_in[2];
    const float* lin_w  = (const float*)d_in[3];
    const float* lin_b  = (const float*)d_in[4];
    const float* ker_w  = (const float*)d_in[5];
    const float* ker_b  = (const float*)d_in[6];
    const float* root_w = (const float*)d_in[7];
    const float* conv_b = (const float*)d_in[8];
    const float* mu_w   = (const float*)d_in[9];
    const float* mu_b   = (const float*)d_in[10];
    const float* lv_w   = (const float*)d_in[11];
    const float* lv_b   = (const float*)d_in[12];

    int N = in_sizes[0] / IN_DIM;
    int E = in_sizes[1] / 2;
    if (N > NMAX) N = NMAX;
    if (E > EMAX) E = EMAX;

    cudaFuncSetAttribute(edge_kernel, cudaFuncAttributeMaxDynamicSharedMemorySize,
                         SMEM_EDGE);

    detect_kernel<<<1, 1>>>((const int*)ei);
    zero_kernel<<<256, 256>>>(N);
    prep_kernel<<<256, 256>>>(ker_w);
    convert_kernel<<<(E + 255) / 256, 256>>>(ei, E);
    hin_kernel<<<(N + 15) / 16, 128>>>(x, lin_w, lin_b, N);
    edge_kernel<<<(E + 127) / 128, 256, SMEM_EDGE>>>(ea, ker_b, E);
    final_kernel<<<(N + 15) / 16, 256>>>(root_w, conv_b, mu_w, mu_b, lv_w, lv_b,
                                         (float*)d_out, N);
}

// round 5
// speedup vs baseline: 2.4312x; 1.1671x over previous
#include <cuda_runtime.h>
#include <cuda_bf16.h>
#include <cstdint>

// Problem constants (shapes fixed by the reference: N=20000, E=100000)
#define NMAX 20000
#define EMAX 100000
constexpr int IN_DIM = 128;
constexpr int HID    = 64;
constexpr int LAT    = 32;
constexpr int EDIM   = 16;

// ---------------- edge kernel geometry --------------------------------------
// 256 threads = 8 warps; 128 edges per CTA (warp w owns edges 16w..16w+15).
// B (ker_w hi/lo bf16) prepped in global with 48B row stride; bias (256 f32)
// appended per chunk so it streams through the same cp.async path.
constexpr int B_CHUNK_BYTES = 256 * 48;          // per term: 12288
constexpr int B_BIAS_OFF    = 2 * B_CHUNK_BYTES; // 24576
constexpr int B_SLOT_BYTES  = B_BIAS_OFF + 1024; // hi + lo + bias: 25600
constexpr int NCHUNK        = 16;

// dynamic smem layout (16B aligned blocks)
constexpr int SMB_H    = 0;                       // 128 rows * 272B = 34816
constexpr int SMB_A    = 34816;                   // 2 terms * 128*48 = 12288
constexpr int SMB_B    = SMB_A + 12288;           // 2 slots * 25600 = 51200
constexpr int SMEM_EDGE = SMB_B + 2 * B_SLOT_BYTES;   // 98304 (2 CTAs/SM)

// ---------------- scratch (device globals; no cudaMalloc allowed) -----------
__device__ float g_h[NMAX * HID];
__device__ float g_num[NMAX * HID];
__device__ float g_cnt[NMAX];
__device__ int   g_src[EMAX];
__device__ int   g_dst[EMAX];
__device__ int   g_is64;
__device__ __align__(16) unsigned char g_Bp[NCHUNK * B_SLOT_BYTES]; // 400KB

// ---------------- helpers ----------------------------------------------------
typedef unsigned long long u64;

__device__ __forceinline__ u64 pk2(float x, float y) {
    u64 r; asm("mov.b64 %0,{%1,%2};" : "=l"(r) : "f"(x), "f"(y)); return r;
}
__device__ __forceinline__ void upk2(u64 v, float& x, float& y) {
    asm("mov.b64 {%0,%1},%2;" : "=f"(x), "=f"(y) : "l"(v));
}
__device__ __forceinline__ u64 ffma2(u64 a, u64 b, u64 c) {
    u64 d; asm("fma.rn.f32x2 %0,%1,%2,%3;" : "=l"(d) : "l"(a), "l"(b), "l"(c)); return d;
}
__device__ __forceinline__ unsigned smem_u32(const void* p) {
    return (unsigned)__cvta_generic_to_shared(p);
}
__device__ __forceinline__ void cpasync16(unsigned dst, const void* src) {
    asm volatile("cp.async.ca.shared.global [%0], [%1], 16;" :: "r"(dst), "l"(src));
}
#define CP_COMMIT() asm volatile("cp.async.commit_group;" ::: "memory")
#define CP_WAIT0()  asm volatile("cp.async.wait_group 0;" ::: "memory")

#define LDMX2(r0, r1, addr) \
    asm volatile("ldmatrix.sync.aligned.m8n8.x2.shared.b16 {%0,%1},[%2];" \
                 : "=r"(r0), "=r"(r1) : "r"(addr))
#define LDMX4(r, addr) \
    asm volatile("ldmatrix.sync.aligned.m8n8.x4.shared.b16 {%0,%1,%2,%3},[%4];" \
                 : "=r"((r)[0]), "=r"((r)[1]), "=r"((r)[2]), "=r"((r)[3]) : "r"(addr))

#define MMA_BF16(c0, c1, c2, c3, a, b0, b1) \
    asm volatile("mma.sync.aligned.m16n8k16.row.col.f32.bf16.bf16.f32 " \
                 "{%0,%1,%2,%3},{%4,%5,%6,%7},{%8,%9},{%0,%1,%2,%3};" \
                 : "+f"(c0), "+f"(c1), "+f"(c2), "+f"(c3) \
                 : "r"((a)[0]), "r"((a)[1]), "r"((a)[2]), "r"((a)[3]), \
                   "r"(b0), "r"(b1))

// ---------------- setup: detect + zero + prep (one launch) -------------------
__global__ void setup_kernel(const int* __restrict__ ei,
                             const float* __restrict__ kw,
                             const float* __restrict__ kb, int N) {
    int gtid = blockIdx.x * 256 + threadIdx.x;
    int gsz  = gridDim.x * 256;
    if (gtid == 0) {
        int is64 = 1;
#pragma unroll
        for (int k = 0; k < 32; k++)
            if (ei[2 * k + 1] != 0) is64 = 0;
        g_is64 = is64;
    }
    // zero accumulators
    int tot = N * HID;
    for (int i = gtid; i < tot; i += gsz) g_num[i] = 0.f;
    for (int j = gtid; j < N; j += gsz)   g_cnt[j] = 0.f;
    // prep B images: hi/lo bf16 with 48B row stride (pad bytes stay 0-init)
    for (int idx = gtid; idx < 4096 * 16; idx += gsz) {
        int n = idx >> 4, k = idx & 15;
        float v = kw[(size_t)k * 4096 + n];
        __nv_bfloat16 hi = __float2bfloat16_rn(v);
        __nv_bfloat16 lo = __float2bfloat16_rn(v - __bfloat162float(hi));
        int c = n >> 8, nl = n & 255;
        size_t base = (size_t)c * B_SLOT_BYTES + (size_t)nl * 48 + (size_t)k * 2;
        *(__nv_bfloat16*)(g_Bp + base)                 = hi;
        *(__nv_bfloat16*)(g_Bp + base + B_CHUNK_BYTES) = lo;
    }
    // bias appended per chunk
    for (int n = gtid; n < 4096; n += gsz) {
        int c = n >> 8, nl = n & 255;
        *(float*)(g_Bp + (size_t)c * B_SLOT_BYTES + B_BIAS_OFF + (size_t)nl * 4) = kb[n];
    }
}

__global__ void convert_kernel(const void* __restrict__ ei, int E) {
    int e = blockIdx.x * blockDim.x + threadIdx.x;
    if (e >= E) return;
    int s, d;
    if (g_is64) {
        const long long* p = (const long long*)ei;
        s = (int)p[e]; d = (int)p[E + e];
    } else {
        const int* p = (const int*)ei;
        s = p[e]; d = p[E + e];
    }
    g_src[e] = s; g_dst[e] = d;
    atomicAdd(&g_cnt[d], 1.f);
}

// ---------------- h = relu(x @ lin_in_w + lin_in_b) -------------------------
__global__ void __launch_bounds__(128) hin_kernel(
    const float* __restrict__ x, const float* __restrict__ w,
    const float* __restrict__ b, int N) {
    __shared__ u64   ws2[IN_DIM][32];   // (w[d][2p], w[d][2p+1])
    __shared__ float xs[16][IN_DIM];
    int tid = threadIdx.x;
    for (int i = tid; i < IN_DIM * 32; i += 128)
        ((u64*)ws2)[i] = ((const u64*)w)[i];
    int base = blockIdx.x * 16;
    for (int i = tid; i < 16 * 32; i += 128) {
        int nl = i >> 5, j = i & 31;
        int n = base + nl;
        if (n < N) ((float4*)xs[nl])[j] = ((const float4*)(x + (size_t)n * IN_DIM))[j];
    }
    __syncthreads();
    int p = tid & 31, g = tid >> 5;
    float2 b2 = ((const float2*)b)[p];
    u64 bias2 = pk2(b2.x, b2.y);
    u64 acc0 = bias2, acc1 = bias2, acc2 = bias2, acc3 = bias2;
#pragma unroll 8
    for (int d = 0; d < IN_DIM; d++) {
        u64 w2 = ws2[d][p];
        acc0 = ffma2(pk2(xs[g][d],      xs[g][d]),      w2, acc0);
        acc1 = ffma2(pk2(xs[g + 4][d],  xs[g + 4][d]),  w2, acc1);
        acc2 = ffma2(pk2(xs[g + 8][d],  xs[g + 8][d]),  w2, acc2);
        acc3 = ffma2(pk2(xs[g + 12][d], xs[g + 12][d]), w2, acc3);
    }
    u64 accs[4] = {acc0, acc1, acc2, acc3};
#pragma unroll
    for (int q = 0; q < 4; q++) {
        int n = base + g + 4 * q;
        if (n < N) {
            float v0, v1; upk2(accs[q], v0, v1);
            float2 r; r.x = fmaxf(v0, 0.f); r.y = fmaxf(v1, 0.f);
            *(float2*)(g_h + (size_t)n * HID + 2 * p) = r;
        }
    }
}

// ---------------- fused edge kernel (mma.sync bf16 3-term) -------------------
// msg[e,o] = sum_h h_src[e,h] * relu( (EA[e,:]@K)[h*64+o] + kb[h*64+o] )
__global__ void __launch_bounds__(256, 2) edge_kernel(
    const float* __restrict__ edge_attr, int E) {
    extern __shared__ __align__(16) unsigned char sm[];
    unsigned sb = smem_u32(sm);
    int tid = threadIdx.x, lane = tid & 31, w = tid >> 5;
    int blk = blockIdx.x;

    // stage h rows (gather; row stride 272B -> conflict-free scalar reads)
    for (int i = tid; i < 128 * 16; i += 256) {
        int r = i >> 4, q4 = i & 15;
        int e = blk * 128 + r;
        int s = (e < E) ? g_src[e] : 0;
        *(float4*)(sm + SMB_H + r * 272 + q4 * 16) =
            ((const float4*)(g_h + (size_t)s * HID))[q4];
    }

    // stage A rows (hi/lo bf16, 48B stride); zero rows for edges >= E
    if (tid < 128) {
        int e = blk * 128 + tid;
        float va[16];
        if (e < E) {
            const float4* p = (const float4*)(edge_attr + (size_t)e * EDIM);
#pragma unroll
            for (int i = 0; i < 4; i++) {
                float4 q4 = p[i];
                va[4*i] = q4.x; va[4*i+1] = q4.y; va[4*i+2] = q4.z; va[4*i+3] = q4.w;
            }
        } else {
#pragma unroll
            for (int i = 0; i < 16; i++) va[i] = 0.f;
        }
#pragma unroll
        for (int k = 0; k < 8; k++) {
            float v0 = va[2*k], v1 = va[2*k+1];
            __nv_bfloat16 h0 = __float2bfloat16_rn(v0);
            __nv_bfloat16 h1 = __float2bfloat16_rn(v1);
            __nv_bfloat162 hp; hp.x = h0; hp.y = h1;
            __nv_bfloat162 lp;
            lp.x = __float2bfloat16_rn(v0 - __bfloat162float(h0));
            lp.y = __float2bfloat16_rn(v1 - __bfloat162float(h1));
            *(__nv_bfloat162*)(sm + SMB_A + tid * 48 + k * 4)        = hp;
            *(__nv_bfloat162*)(sm + SMB_A + 6144 + tid * 48 + k * 4) = lp;
        }
    }

    // stage B chunk 0 (hi + lo + bias, flat copy)
    for (int i = tid; i < B_SLOT_BYTES / 16; i += 256)
        cpasync16(sb + SMB_B + i * 16, g_Bp + i * 16);
    CP_COMMIT();
    CP_WAIT0();
    __syncthreads();

    // A fragments (register resident for the whole kernel)
    unsigned a_hi[4], a_lo[4];
    {
        int rowA = (lane & 7) + ((lane >> 3) & 1) * 8;
        int koff = (lane >> 4) * 8;
        unsigned aaddr = sb + SMB_A + (unsigned)((w * 16 + rowA) * 48 + koff * 2);
        LDMX4(a_hi, aaddr);
        LDMX4(a_lo, aaddr + 6144);
    }

    int q = lane & 3;
    int row0 = lane >> 2;                       // warp-tile local row (0..7)
    unsigned hrow0 = sb + SMB_H + (unsigned)((w * 16 + row0) * 272);
    unsigned hrow1 = hrow0 + 8 * 272;
    unsigned boff  = (unsigned)((lane & 7) * 48 + ((lane & 8) ? 16 : 0));

    float msgA[16], msgB[16];
#pragma unroll
    for (int i = 0; i < 16; i++) { msgA[i] = 0.f; msgB[i] = 0.f; }

    for (int c = 0; c < NCHUNK; c++) {
        int slot = c & 1;
        if (c < NCHUNK - 1) {                   // prefetch next chunk
            const unsigned char* src = g_Bp + (size_t)(c + 1) * B_SLOT_BYTES;
            unsigned dstb = sb + SMB_B + (unsigned)(((c + 1) & 1) * B_SLOT_BYTES);
            for (int i = tid; i < B_SLOT_BYTES / 16; i += 256)
                cpasync16(dstb + i * 16, src + i * 16);
            CP_COMMIT();
        }
        unsigned slotbase = sb + SMB_B + (unsigned)(slot * B_SLOT_BYTES);
        unsigned bbase = slotbase + boff;
        unsigned biasb = slotbase + (unsigned)B_BIAS_OFF + (unsigned)(q * 8);
#pragma unroll
        for (int hb = 0; hb < 4; hb++) {
            int h = c * 4 + hb;
            float hv0, hv1;
            asm("ld.shared.f32 %0,[%1];" : "=f"(hv0) : "r"(hrow0 + (unsigned)(h * 4)));
            asm("ld.shared.f32 %0,[%1];" : "=f"(hv1) : "r"(hrow1 + (unsigned)(h * 4)));
#pragma unroll
            for (int t = 0; t < 8; t++) {
                int jj = hb * 8 + t;            // n-step within chunk
                unsigned ba = bbase + (unsigned)(jj * 384);
                unsigned bh0, bh1, bl0, bl1;
                LDMX2(bh0, bh1, ba);
                LDMX2(bl0, bl1, ba + B_CHUNK_BYTES);
                float c0 = 0.f, c1 = 0.f, c2 = 0.f, c3 = 0.f;
                MMA_BF16(c0, c1, c2, c3, a_hi, bh0, bh1);
                MMA_BF16(c0, c1, c2, c3, a_lo, bh0, bh1);
                MMA_BF16(c0, c1, c2, c3, a_hi, bl0, bl1);
                float2 bb;
                asm("ld.shared.v2.f32 {%0,%1},[%2];"
                    : "=f"(bb.x), "=f"(bb.y)
                    : "r"(biasb + (unsigned)(jj * 32)));
                float w0 = fmaxf(c0 + bb.x, 0.f);
                float w1 = fmaxf(c1 + bb.y, 0.f);
                float w2 = fmaxf(c2 + bb.x, 0.f);
                float w3 = fmaxf(c3 + bb.y, 0.f);
                msgA[t*2]     = fmaf(hv0, w0, msgA[t*2]);
                msgA[t*2 + 1] = fmaf(hv0, w1, msgA[t*2 + 1]);
                msgB[t*2]     = fmaf(hv1, w2, msgB[t*2]);
                msgB[t*2 + 1] = fmaf(hv1, w3, msgB[t*2 + 1]);
            }
        }
        if (c < NCHUNK - 1) CP_WAIT0();
        __syncthreads();
    }

    // scatter: each (edge, o) has a unique owner thread
    int e0 = blk * 128 + w * 16 + row0;
    if (e0 < E) {
        float* d = g_num + (size_t)g_dst[e0] * HID + 2 * q;
#pragma unroll
        for (int t = 0; t < 8; t++) {
            atomicAdd(d + 8 * t,     msgA[2 * t]);
            atomicAdd(d + 8 * t + 1, msgA[2 * t + 1]);
        }
    }
    int e1 = e0 + 8;
    if (e1 < E) {
        float* d = g_num + (size_t)g_dst[e1] * HID + 2 * q;
#pragma unroll
        for (int t = 0; t < 8; t++) {
            atomicAdd(d + 8 * t,     msgB[2 * t]);
            atomicAdd(d + 8 * t + 1, msgB[2 * t + 1]);
        }
    }
}

// ---------------- final: relu(h@root_w + num/cnt + conv_b) -> mu/logvar -----
__global__ void __launch_bounds__(256) final_kernel(
    const float* __restrict__ root_w, const float* __restrict__ conv_b,
    const float* __restrict__ mu_w, const float* __restrict__ mu_b,
    const float* __restrict__ lv_w, const float* __restrict__ lv_b,
    float* __restrict__ out, int N) {
    __shared__ float rw[HID][HID];
    __shared__ float mw[HID][LAT];
    __shared__ float lw[HID][LAT];
    __shared__ float hv[4][HID];
    __shared__ float tv[4][HID];
    int tid = threadIdx.x;
    for (int idx = tid; idx < HID * HID / 4; idx += 256)
        ((float4*)rw)[idx] = ((const float4*)root_w)[idx];
    for (int idx = tid; idx < HID * LAT / 4; idx += 256)
        ((float4*)mw)[idx] = ((const float4*)mu_w)[idx];
    for (int idx = tid; idx < HID * LAT / 4; idx += 256)
        ((float4*)lw)[idx] = ((const float4*)lv_w)[idx];
    __syncthreads();

    int g = tid >> 6;
    int o = tid & 63;
    float cb = conv_b[o];
    float hb = (o < LAT) ? mu_b[o] : lv_b[o - LAT];

    for (int nl = g; nl < 16; nl += 4) {
        int n = blockIdx.x * 16 + nl;
        bool valid = n < N;
        if (valid) hv[g][o] = g_h[(size_t)n * HID + o];
        asm volatile("bar.sync %0, 64;" :: "r"(g + 1) : "memory");
        if (valid) {
            float inv = 1.f / fmaxf(g_cnt[n], 1.f);
            float acc = cb + g_num[(size_t)n * HID + o] * inv;
#pragma unroll
            for (int h = 0; h < HID; h++) acc += hv[g][h] * rw[h][o];
            tv[g][o] = fmaxf(acc, 0.f);
        }
        asm volatile("bar.sync %0, 64;" :: "r"(g + 1) : "memory");
        if (valid) {
            if (o < LAT) {
                float m = hb;
#pragma unroll
                for (int k = 0; k < HID; k++) m += tv[g][k] * mw[k][o];
                out[(size_t)n * LAT + o] = m;
            } else {
                int l = o - LAT;
                float m = hb;
#pragma unroll
                for (int k = 0; k < HID; k++) m += tv[g][k] * lw[k][l];
                out[(size_t)N * LAT + (size_t)n * LAT + l] = m;
            }
        }
        asm volatile("bar.sync %0, 64;" :: "r"(g + 1) : "memory");
    }
}

// ---------------- launcher ---------------------------------------------------
extern "C" void kernel_launch(void* const* d_in, const int* in_sizes, int n_in,
                              void* d_out, int out_size) {
    const float* x      = (const float*)d_in[0];
    const void*  ei     = d_in[1];
    const float* ea     = (const float*)d_in[2];
    const float* lin_w  = (const float*)d_in[3];
    const float* lin_b  = (const float*)d_in[4];
    const float* ker_w  = (const float*)d_in[5];
    const float* ker_b  = (const float*)d_in[6];
    const float* root_w = (const float*)d_in[7];
    const float* conv_b = (const float*)d_in[8];
    const float* mu_w   = (const float*)d_in[9];
    const float* mu_b   = (const float*)d_in[10];
    const float* lv_w   = (const float*)d_in[11];
    const float* lv_b   = (const float*)d_in[12];

    int N = in_sizes[0] / IN_DIM;
    int E = in_sizes[1] / 2;
    if (N > NMAX) N = NMAX;
    if (E > EMAX) E = EMAX;

    cudaFuncSetAttribute(edge_kernel, cudaFuncAttributeMaxDynamicSharedMemorySize,
                         SMEM_EDGE);

    setup_kernel<<<640, 256>>>((const int*)ei, ker_w, ker_b, N);
    convert_kernel<<<(E + 255) / 256, 256>>>(ei, E);
    hin_kernel<<<(N + 15) / 16, 128>>>(x, lin_w, lin_b, N);
    edge_kernel<<<(E + 127) / 128, 256, SMEM_EDGE>>>(ea, E);
    final_kernel<<<(N + 15) / 16, 256>>>(root_w, conv_b, mu_w, mu_b, lv_w, lv_b,
                                         (float*)d_out, N);
}

// round 6
// speedup vs baseline: 2.6361x; 1.0843x over previous
#include <cuda_runtime.h>
#include <cuda_bf16.h>
#include <cstdint>

// Problem constants (shapes fixed by the reference: N=20000, E=100000)
#define NMAX 20000
#define EMAX 100000
constexpr int IN_DIM = 128;
constexpr int HID    = 64;
constexpr int LAT    = 32;
constexpr int EDIM   = 16;

// ---------------- edge kernel geometry --------------------------------------
// 256 threads = 8 warps; 128 edges per CTA (warp w owns edges 16w..16w+15).
// B (ker_w hi/lo bf16) prepped in global with 48B row stride; bias (256 f32)
// appended per chunk so it streams through the same cp.async path.
constexpr int B_CHUNK_BYTES = 256 * 48;          // per term: 12288
constexpr int B_BIAS_OFF    = 2 * B_CHUNK_BYTES; // 24576
constexpr int B_SLOT_BYTES  = B_BIAS_OFF + 1024; // hi + lo + bias: 25600
constexpr int NCHUNK        = 16;

// dynamic smem layout (16B aligned blocks). No H stage (h read via LDG from L2).
constexpr int SMB_A    = 0;                       // 2 terms * 128*48 = 12288
constexpr int SMB_B    = 12288;                   // 2 slots * 25600 = 51200
constexpr int SMEM_EDGE = SMB_B + 2 * B_SLOT_BYTES;   // 63488 (3 CTAs/SM)

// ---------------- scratch (device globals; no cudaMalloc allowed) -----------
__device__ float g_h[NMAX * HID];
__device__ float g_num[NMAX * HID];
__device__ float g_cnt[NMAX];
__device__ int   g_src[EMAX];
__device__ int   g_dst[EMAX];
__device__ int   g_is64;
__device__ __align__(16) unsigned char g_Bp[NCHUNK * B_SLOT_BYTES]; // 400KB

// ---------------- helpers ----------------------------------------------------
typedef unsigned long long u64;

__device__ __forceinline__ u64 pk2(float x, float y) {
    u64 r; asm("mov.b64 %0,{%1,%2};" : "=l"(r) : "f"(x), "f"(y)); return r;
}
__device__ __forceinline__ void upk2(u64 v, float& x, float& y) {
    asm("mov.b64 {%0,%1},%2;" : "=f"(x), "=f"(y) : "l"(v));
}
__device__ __forceinline__ u64 ffma2(u64 a, u64 b, u64 c) {
    u64 d; asm("fma.rn.f32x2 %0,%1,%2,%3;" : "=l"(d) : "l"(a), "l"(b), "l"(c)); return d;
}
__device__ __forceinline__ unsigned smem_u32(const void* p) {
    return (unsigned)__cvta_generic_to_shared(p);
}
__device__ __forceinline__ void cpasync16(unsigned dst, const void* src) {
    asm volatile("cp.async.ca.shared.global [%0], [%1], 16;" :: "r"(dst), "l"(src));
}
#define CP_COMMIT() asm volatile("cp.async.commit_group;" ::: "memory")
#define CP_WAIT0()  asm volatile("cp.async.wait_group 0;" ::: "memory")

#define LDMX4(r, addr) \
    asm volatile("ldmatrix.sync.aligned.m8n8.x4.shared.b16 {%0,%1,%2,%3},[%4];" \
                 : "=r"((r)[0]), "=r"((r)[1]), "=r"((r)[2]), "=r"((r)[3]) : "r"(addr))

#define MMA_BF16(c0, c1, c2, c3, a, b0, b1) \
    asm volatile("mma.sync.aligned.m16n8k16.row.col.f32.bf16.bf16.f32 " \
                 "{%0,%1,%2,%3},{%4,%5,%6,%7},{%8,%9},{%0,%1,%2,%3};" \
                 : "+f"(c0), "+f"(c1), "+f"(c2), "+f"(c3) \
                 : "r"((a)[0]), "r"((a)[1]), "r"((a)[2]), "r"((a)[3]), \
                   "r"(b0), "r"(b1))

// ---------------- setup: detect + zero + prep (one launch) -------------------
__global__ void setup_kernel(const int* __restrict__ ei,
                             const float* __restrict__ kw,
                             const float* __restrict__ kb, int N) {
    int gtid = blockIdx.x * 256 + threadIdx.x;
    int gsz  = gridDim.x * 256;
    if (gtid == 0) {
        int is64 = 1;
#pragma unroll
        for (int k = 0; k < 32; k++)
            if (ei[2 * k + 1] != 0) is64 = 0;
        g_is64 = is64;
    }
    // zero accumulators
    int tot = N * HID;
    for (int i = gtid; i < tot; i += gsz) g_num[i] = 0.f;
    for (int j = gtid; j < N; j += gsz)   g_cnt[j] = 0.f;
    // prep B images: hi/lo bf16 with 48B row stride (pad bytes stay 0-init)
    for (int idx = gtid; idx < 4096 * 16; idx += gsz) {
        int n = idx >> 4, k = idx & 15;
        float v = kw[(size_t)k * 4096 + n];
        __nv_bfloat16 hi = __float2bfloat16_rn(v);
        __nv_bfloat16 lo = __float2bfloat16_rn(v - __bfloat162float(hi));
        int c = n >> 8, nl = n & 255;
        size_t base = (size_t)c * B_SLOT_BYTES + (size_t)nl * 48 + (size_t)k * 2;
        *(__nv_bfloat16*)(g_Bp + base)                 = hi;
        *(__nv_bfloat16*)(g_Bp + base + B_CHUNK_BYTES) = lo;
    }
    // bias appended per chunk
    for (int n = gtid; n < 4096; n += gsz) {
        int c = n >> 8, nl = n & 255;
        *(float*)(g_Bp + (size_t)c * B_SLOT_BYTES + B_BIAS_OFF + (size_t)nl * 4) = kb[n];
    }
}

__global__ void convert_kernel(const void* __restrict__ ei, int E) {
    int e = blockIdx.x * blockDim.x + threadIdx.x;
    if (e >= E) return;
    int s, d;
    if (g_is64) {
        const long long* p = (const long long*)ei;
        s = (int)p[e]; d = (int)p[E + e];
    } else {
        const int* p = (const int*)ei;
        s = p[e]; d = p[E + e];
    }
    g_src[e] = s; g_dst[e] = d;
    atomicAdd(&g_cnt[d], 1.f);
}

// ---------------- h = relu(x @ lin_in_w + lin_in_b) -------------------------
__global__ void __launch_bounds__(128) hin_kernel(
    const float* __restrict__ x, const float* __restrict__ w,
    const float* __restrict__ b, int N) {
    __shared__ u64   ws2[IN_DIM][32];   // (w[d][2p], w[d][2p+1])
    __shared__ float xs[16][IN_DIM];
    int tid = threadIdx.x;
    for (int i = tid; i < IN_DIM * 32; i += 128)
        ((u64*)ws2)[i] = ((const u64*)w)[i];
    int base = blockIdx.x * 16;
    for (int i = tid; i < 16 * 32; i += 128) {
        int nl = i >> 5, j = i & 31;
        int n = base + nl;
        if (n < N) ((float4*)xs[nl])[j] = ((const float4*)(x + (size_t)n * IN_DIM))[j];
    }
    __syncthreads();
    int p = tid & 31, g = tid >> 5;
    float2 b2 = ((const float2*)b)[p];
    u64 bias2 = pk2(b2.x, b2.y);
    u64 acc0 = bias2, acc1 = bias2, acc2 = bias2, acc3 = bias2;
#pragma unroll 8
    for (int d = 0; d < IN_DIM; d++) {
        u64 w2 = ws2[d][p];
        acc0 = ffma2(pk2(xs[g][d],      xs[g][d]),      w2, acc0);
        acc1 = ffma2(pk2(xs[g + 4][d],  xs[g + 4][d]),  w2, acc1);
        acc2 = ffma2(pk2(xs[g + 8][d],  xs[g + 8][d]),  w2, acc2);
        acc3 = ffma2(pk2(xs[g + 12][d], xs[g + 12][d]), w2, acc3);
    }
    u64 accs[4] = {acc0, acc1, acc2, acc3};
#pragma unroll
    for (int q = 0; q < 4; q++) {
        int n = base + g + 4 * q;
        if (n < N) {
            float v0, v1; upk2(accs[q], v0, v1);
            float2 r; r.x = fmaxf(v0, 0.f); r.y = fmaxf(v1, 0.f);
            *(float2*)(g_h + (size_t)n * HID + 2 * p) = r;
        }
    }
}

// ---------------- fused edge kernel (mma.sync bf16 3-term) -------------------
// msg[e,o] = sum_h h_src[e,h] * relu( (EA[e,:]@K)[h*64+o] + kb[h*64+o] )
__global__ void __launch_bounds__(256, 3) edge_kernel(
    const float* __restrict__ edge_attr, int E) {
    extern __shared__ __align__(16) unsigned char sm[];
    unsigned sb = smem_u32(sm);
    int tid = threadIdx.x, lane = tid & 31, w = tid >> 5;
    int blk = blockIdx.x;

    // stage A rows (hi/lo bf16, 48B stride); zero rows for edges >= E
    if (tid < 128) {
        int e = blk * 128 + tid;
        float va[16];
        if (e < E) {
            const float4* p = (const float4*)(edge_attr + (size_t)e * EDIM);
#pragma unroll
            for (int i = 0; i < 4; i++) {
                float4 q4 = p[i];
                va[4*i] = q4.x; va[4*i+1] = q4.y; va[4*i+2] = q4.z; va[4*i+3] = q4.w;
            }
        } else {
#pragma unroll
            for (int i = 0; i < 16; i++) va[i] = 0.f;
        }
#pragma unroll
        for (int k = 0; k < 8; k++) {
            float v0 = va[2*k], v1 = va[2*k+1];
            __nv_bfloat16 h0 = __float2bfloat16_rn(v0);
            __nv_bfloat16 h1 = __float2bfloat16_rn(v1);
            __nv_bfloat162 hp; hp.x = h0; hp.y = h1;
            __nv_bfloat162 lp;
            lp.x = __float2bfloat16_rn(v0 - __bfloat162float(h0));
            lp.y = __float2bfloat16_rn(v1 - __bfloat162float(h1));
            *(__nv_bfloat162*)(sm + SMB_A + tid * 48 + k * 4)        = hp;
            *(__nv_bfloat162*)(sm + SMB_A + 6144 + tid * 48 + k * 4) = lp;
        }
    }

    // stage B chunk 0 (hi + lo + bias, flat copy)
    for (int i = tid; i < B_SLOT_BYTES / 16; i += 256)
        cpasync16(sb + SMB_B + i * 16, g_Bp + i * 16);
    CP_COMMIT();
    CP_WAIT0();
    __syncthreads();

    // A fragments (register resident for the whole kernel)
    unsigned a_hi[4], a_lo[4];
    {
        int rowA = (lane & 7) + ((lane >> 3) & 1) * 8;
        int koff = (lane >> 4) * 8;
        unsigned aaddr = sb + SMB_A + (unsigned)((w * 16 + rowA) * 48 + koff * 2);
        LDMX4(a_hi, aaddr);
        LDMX4(a_lo, aaddr + 6144);
    }

    int q = lane & 3;
    int row0 = lane >> 2;                       // warp-tile local row (0..7)
    int e0 = blk * 128 + w * 16 + row0;
    int e1 = e0 + 8;
    const float4* hp0 = (const float4*)(g_h + (size_t)((e0 < E) ? g_src[e0] : 0) * HID);
    const float4* hp1 = (const float4*)(g_h + (size_t)((e1 < E) ? g_src[e1] : 0) * HID);
    // ldmatrix.x4 lane->addr: m0/m1 = jj0 (k lo/hi halves), m2/m3 = jj0+1
    unsigned bext = (unsigned)((lane & 7) * 48 + ((lane & 8) ? 16 : 0)
                               + ((lane & 16) ? 384 : 0));

    float msgA[16], msgB[16];
#pragma unroll
    for (int i = 0; i < 16; i++) { msgA[i] = 0.f; msgB[i] = 0.f; }

    for (int c = 0; c < NCHUNK; c++) {
        int slot = c & 1;
        if (c < NCHUNK - 1) {                   // prefetch next chunk
            const unsigned char* src = g_Bp + (size_t)(c + 1) * B_SLOT_BYTES;
            unsigned dstb = sb + SMB_B + (unsigned)(((c + 1) & 1) * B_SLOT_BYTES);
            for (int i = tid; i < B_SLOT_BYTES / 16; i += 256)
                cpasync16(dstb + i * 16, src + i * 16);
            CP_COMMIT();
        }
        unsigned slotbase = sb + SMB_B + (unsigned)(slot * B_SLOT_BYTES);
        unsigned bhib  = slotbase + bext;
        unsigned biasb = slotbase + (unsigned)B_BIAS_OFF + (unsigned)(q * 8);
        float4 hv0 = __ldg(hp0 + c);
        float4 hv1 = __ldg(hp1 + c);
        float h0a[4] = {hv0.x, hv0.y, hv0.z, hv0.w};
        float h1a[4] = {hv1.x, hv1.y, hv1.z, hv1.w};
#pragma unroll
        for (int hb = 0; hb < 4; hb++) {
            float hs0 = h0a[hb], hs1 = h1a[hb];
#pragma unroll
            for (int jp = 0; jp < 4; jp++) {
                int jj0 = hb * 8 + jp * 2;      // pair of n-steps
                unsigned ba = bhib + (unsigned)(jj0 * 384);
                unsigned bh[4], bl[4];
                LDMX4(bh, ba);
                LDMX4(bl, ba + B_CHUNK_BYTES);
                // jj0: C-init from bias, 3-term MMA
                float c0, c1, c2, c3;
                asm("ld.shared.v2.f32 {%0,%1},[%2];"
                    : "=f"(c0), "=f"(c1) : "r"(biasb + (unsigned)(jj0 * 32)));
                c2 = c0; c3 = c1;
                MMA_BF16(c0, c1, c2, c3, a_hi, bh[0], bh[1]);
                MMA_BF16(c0, c1, c2, c3, a_lo, bh[0], bh[1]);
                MMA_BF16(c0, c1, c2, c3, a_hi, bl[0], bl[1]);
                // jj1
                float d0, d1, d2, d3;
                asm("ld.shared.v2.f32 {%0,%1},[%2];"
                    : "=f"(d0), "=f"(d1) : "r"(biasb + (unsigned)(jj0 * 32 + 32)));
                d2 = d0; d3 = d1;
                MMA_BF16(d0, d1, d2, d3, a_hi, bh[2], bh[3]);
                MMA_BF16(d0, d1, d2, d3, a_lo, bh[2], bh[3]);
                MMA_BF16(d0, d1, d2, d3, a_hi, bl[2], bl[3]);
                // epilogue: relu + h-weighted accumulate
                int m = 4 * jp;
                msgA[m]     = fmaf(hs0, fmaxf(c0, 0.f), msgA[m]);
                msgA[m + 1] = fmaf(hs0, fmaxf(c1, 0.f), msgA[m + 1]);
                msgB[m]     = fmaf(hs1, fmaxf(c2, 0.f), msgB[m]);
                msgB[m + 1] = fmaf(hs1, fmaxf(c3, 0.f), msgB[m + 1]);
                msgA[m + 2] = fmaf(hs0, fmaxf(d0, 0.f), msgA[m + 2]);
                msgA[m + 3] = fmaf(hs0, fmaxf(d1, 0.f), msgA[m + 3]);
                msgB[m + 2] = fmaf(hs1, fmaxf(d2, 0.f), msgB[m + 2]);
                msgB[m + 3] = fmaf(hs1, fmaxf(d3, 0.f), msgB[m + 3]);
            }
        }
        if (c < NCHUNK - 1) CP_WAIT0();
        __syncthreads();
    }

    // scatter: each (edge, o) has a unique owner thread
    if (e0 < E) {
        float* d = g_num + (size_t)g_dst[e0] * HID + 2 * q;
#pragma unroll
        for (int t = 0; t < 8; t++) {
            atomicAdd(d + 8 * t,     msgA[2 * t]);
            atomicAdd(d + 8 * t + 1, msgA[2 * t + 1]);
        }
    }
    if (e1 < E) {
        float* d = g_num + (size_t)g_dst[e1] * HID + 2 * q;
#pragma unroll
        for (int t = 0; t < 8; t++) {
            atomicAdd(d + 8 * t,     msgB[2 * t]);
            atomicAdd(d + 8 * t + 1, msgB[2 * t + 1]);
        }
    }
}

// ---------------- final: relu(h@root_w + num/cnt + conv_b) -> mu/logvar -----
__global__ void __launch_bounds__(256) final_kernel(
    const float* __restrict__ root_w, const float* __restrict__ conv_b,
    const float* __restrict__ mu_w, const float* __restrict__ mu_b,
    const float* __restrict__ lv_w, const float* __restrict__ lv_b,
    float* __restrict__ out, int N) {
    __shared__ float rw[HID][HID];
    __shared__ float mw[HID][LAT];
    __shared__ float lw[HID][LAT];
    __shared__ float hv[4][HID];
    __shared__ float tv[4][HID];
    int tid = threadIdx.x;
    for (int idx = tid; idx < HID * HID / 4; idx += 256)
        ((float4*)rw)[idx] = ((const float4*)root_w)[idx];
    for (int idx = tid; idx < HID * LAT / 4; idx += 256)
        ((float4*)mw)[idx] = ((const float4*)mu_w)[idx];
    for (int idx = tid; idx < HID * LAT / 4; idx += 256)
        ((float4*)lw)[idx] = ((const float4*)lv_w)[idx];
    __syncthreads();

    int g = tid >> 6;
    int o = tid & 63;
    float cb = conv_b[o];
    float hb = (o < LAT) ? mu_b[o] : lv_b[o - LAT];

    for (int nl = g; nl < 16; nl += 4) {
        int n = blockIdx.x * 16 + nl;
        bool valid = n < N;
        if (valid) hv[g][o] = g_h[(size_t)n * HID + o];
        asm volatile("bar.sync %0, 64;" :: "r"(g + 1) : "memory");
        if (valid) {
            float inv = 1.f / fmaxf(g_cnt[n], 1.f);
            float acc = cb + g_num[(size_t)n * HID + o] * inv;
#pragma unroll
            for (int h = 0; h < HID; h++) acc += hv[g][h] * rw[h][o];
            tv[g][o] = fmaxf(acc, 0.f);
        }
        asm volatile("bar.sync %0, 64;" :: "r"(g + 1) : "memory");
        if (valid) {
            if (o < LAT) {
                float m = hb;
#pragma unroll
                for (int k = 0; k < HID; k++) m += tv[g][k] * mw[k][o];
                out[(size_t)n * LAT + o] = m;
            } else {
                int l = o - LAT;
                float m = hb;
#pragma unroll
                for (int k = 0; k < HID; k++) m += tv[g][k] * lw[k][l];
                out[(size_t)N * LAT + (size_t)n * LAT + l] = m;
            }
        }
        asm volatile("bar.sync %0, 64;" :: "r"(g + 1) : "memory");
    }
}

// ---------------- launcher ---------------------------------------------------
extern "C" void kernel_launch(void* const* d_in, const int* in_sizes, int n_in,
                              void* d_out, int out_size) {
    const float* x      = (const float*)d_in[0];
    const void*  ei     = d_in[1];
    const float* ea     = (const float*)d_in[2];
    const float* lin_w  = (const float*)d_in[3];
    const float* lin_b  = (const float*)d_in[4];
    const float* ker_w  = (const float*)d_in[5];
    const float* ker_b  = (const float*)d_in[6];
    const float* root_w = (const float*)d_in[7];
    const float* conv_b = (const float*)d_in[8];
    const float* mu_w   = (const float*)d_in[9];
    const float* mu_b   = (const float*)d_in[10];
    const float* lv_w   = (const float*)d_in[11];
    const float* lv_b   = (const float*)d_in[12];

    int N = in_sizes[0] / IN_DIM;
    int E = in_sizes[1] / 2;
    if (N > NMAX) N = NMAX;
    if (E > EMAX) E = EMAX;

    cudaFuncSetAttribute(edge_kernel, cudaFuncAttributeMaxDynamicSharedMemorySize,
                         SMEM_EDGE);

    setup_kernel<<<640, 256>>>((const int*)ei, ker_w, ker_b, N);
    convert_kernel<<<(E + 255) / 256, 256>>>(ei, E);
    hin_kernel<<<(N + 15) / 16, 128>>>(x, lin_w, lin_b, N);
    edge_kernel<<<(E + 127) / 128, 256, SMEM_EDGE>>>(ea, E);
    final_kernel<<<(N + 15) / 16, 256>>>(root_w, conv_b, mu_w, mu_b, lv_w, lv_b,
                                         (float*)d_out, N);
}